// round 15
// baseline (speedup 1.0000x reference)
#include <cuda_runtime.h>
#include <cuda_fp16.h>
#include <cstdint>

#define TT 64
#define BB 128
#define HH 200
#define RROWS 8192      // T*B
#define KTOT 1024       // packed K per channel (320 L + 384 M + 320 R)

// ---------------------------------------------------------------------------
// Scratch (__device__ globals; no cudaMalloc allowed)
// ---------------------------------------------------------------------------
__device__ float g_cur[(size_t)TT * 9 * BB * HH];    // [t][g][b][h]
__device__ __half g_Bh[(size_t)3 * HH * KTOT];       // hi fp16 split of W (K-packed)
__device__ __half g_Bm[(size_t)3 * HH * KTOT];       // lo fp16 split

// ---------------------------------------------------------------------------
// PTX helpers (plain sm_103-compatible: mma.sync / ldmatrix / cp.async)
// ---------------------------------------------------------------------------
__device__ __forceinline__ uint32_t smem_u32(const void* p) {
    uint32_t a;
    asm("{ .reg .u64 t; cvta.to.shared.u64 t, %1; cvt.u32.u64 %0, t; }" : "=r"(a) : "l"(p));
    return a;
}

#define CP16(dst, src) \
    asm volatile("cp.async.cg.shared.global [%0], [%1], 16;" :: "r"(dst), "l"(src) : "memory")
#define CP_COMMIT() asm volatile("cp.async.commit_group;" ::: "memory")
#define CP_WAIT1()  asm volatile("cp.async.wait_group 1;" ::: "memory")

#define LDSM_X4(r, addr) \
    asm volatile("ldmatrix.sync.aligned.m8n8.x4.shared.b16 {%0,%1,%2,%3}, [%4];" \
        : "=r"((r)[0]), "=r"((r)[1]), "=r"((r)[2]), "=r"((r)[3]) : "r"(addr))
#define LDSM_X2(r, addr) \
    asm volatile("ldmatrix.sync.aligned.m8n8.x2.shared.b16 {%0,%1}, [%2];" \
        : "=r"((r)[0]), "=r"((r)[1]) : "r"(addr))

#define MMA16816(d, a, b0, b1) \
    asm volatile("mma.sync.aligned.m16n8k16.row.col.f32.f16.f16.f32 " \
        "{%0,%1,%2,%3},{%4,%5,%6,%7},{%8,%9},{%0,%1,%2,%3};" \
        : "+f"((d)[0]), "+f"((d)[1]), "+f"((d)[2]), "+f"((d)[3]) \
        : "r"((a)[0]), "r"((a)[1]), "r"((a)[2]), "r"((a)[3]), "r"(b0), "r"(b1))

// ---------------------------------------------------------------------------
// Kernel B: split weights into K-packed [c][h][1024] fp16 pairs (vectorized).
// ---------------------------------------------------------------------------
__global__ void convert_w(const float* __restrict__ WL, const float* __restrict__ WM,
                          const float* __restrict__ WR)
{
    int idx2 = blockIdx.x * 256 + threadIdx.x;
    if (idx2 >= 3 * HH * 512) return;
    int q2 = idx2 & 511;
    int ch = idx2 >> 9;                  // c*HH + h
    int q  = q2 * 2;
    float2 v;
    if (q < 320)      v = *(const float2*)&WL[(size_t)ch * 320 + q];
    else if (q < 704) v = *(const float2*)&WM[(size_t)ch * 384 + (q - 320)];
    else              v = *(const float2*)&WR[(size_t)ch * 320 + (q - 704)];
    __half hx = __float2half_rn(v.x), hy = __float2half_rn(v.y);
    __half mx = __float2half_rn(v.x - __half2float(hx));
    __half my = __float2half_rn(v.y - __half2float(hy));
    *(__half2*)&g_Bh[(size_t)ch * KTOT + q] = __halves2half2(hx, hy);
    *(__half2*)&g_Bm[(size_t)ch * KTOT + q] = __halves2half2(mx, my);
}

// ---------------------------------------------------------------------------
// Kernel C: HMMA GEMM, M=64 tiles / 128 threads / 4 warps, 2 blocks per SM
//   (R12 structure).  MMA stream interleaved across the two accumulators of
//   each n-pair (dep distance 2 instead of 1); per-accumulator addition order
//   unchanged (hh -> hm -> mh) => bitwise-identical output.
// ---------------------------------------------------------------------------
#define KCH   32
#define ASTR  40                          // halfs per smem row (A and B)
#define OFF_AM 2560                       // halfs: 64*40
#define OFF_BH 5120                       // halfs: 2*64*40
#define STAGE_HALFS 21120                 // 5120 + 2*8000
#define STAGE_BYTES (STAGE_HALFS * 2)     // 42240
#define GEMM_SMEM (2 * STAGE_BYTES)       // 84480  (x2 blocks = 168960)

__constant__ int c_gmap[9] = {3, 4, 5, 0, 1, 2, 6, 7, 8};   // M part first

__global__ __launch_bounds__(128, 2)
void gemm_mma(const float* __restrict__ x,
              const float* __restrict__ bL, const float* __restrict__ bM,
              const float* __restrict__ bR)
{
    extern __shared__ __half sm[];
    __shared__ int colmap[192];           // x column for even local-q pairs
    const uint32_t smb = smem_u32(sm);
    const int tid = threadIdx.x, wid = tid >> 5, lane = tid & 31;
    const int m_tile = blockIdx.x;        // 0..127, rows m_tile*64..+64
    const int g = c_gmap[blockIdx.y], p = g / 3, c = g - p * 3;

    int Kp, q0, w, off;
    const float* bias;
    if (p == 0)      { Kp = 320; q0 = 0;   w = 10; off = 0;  bias = bL; }
    else if (p == 1) { Kp = 384; q0 = 320; w = 12; off = 10; bias = bM; }
    else             { Kp = 320; q0 = 704; w = 10; off = 22; bias = bR; }
    bias += c * HH;
    const int nch = Kp / KCH;

    for (int q2 = tid; q2 < Kp / 2; q2 += 128) {
        int ql = q2 * 2;
        int grp = ql / w, l = ql - grp * w;
        colmap[q2] = grp * 32 + off + l;
    }
    __syncthreads();

    const float* xc = x + (size_t)m_tile * 64 * 3072 + (size_t)c * 1024;
    const size_t bbase = (size_t)c * HH * KTOT + q0;
    const __half* Bsrc[2] = { g_Bh + bbase, g_Bm + bbase };

    float acc[25][4];
    #pragma unroll
    for (int n = 0; n < 25; n++)
        #pragma unroll
        for (int j = 0; j < 4; j++) acc[n][j] = 0.f;

    // A: 64 rows x 16 float2 = 1024 float2 / 128 thr = 8 per thread
    float2 areg[8];
    auto loadA = [&](int koff) {
        #pragma unroll
        for (int s = 0; s < 8; s++) {
            int i = tid + s * 128;
            int row = i >> 4, j = i & 15;
            areg[s] = *(const float2*)(xc + (size_t)row * 3072 + colmap[(koff >> 1) + j]);
        }
    };
    auto stsA = [&](int buf) {
        __half* base = sm + buf * STAGE_HALFS;
        #pragma unroll
        for (int s = 0; s < 8; s++) {
            int i = tid + s * 128;
            int row = i >> 4, j = i & 15;
            float vx = areg[s].x, vy = areg[s].y;
            __half hx = __float2half_rn(vx), hy = __float2half_rn(vy);
            __half mx = __float2half_rn(vx - __half2float(hx));
            __half my = __float2half_rn(vy - __half2float(hy));
            int pos = row * ASTR + j * 2;
            *(__half2*)(base + pos)          = __halves2half2(hx, hy);
            *(__half2*)(base + OFF_AM + pos) = __halves2half2(mx, my);
        }
    };
    auto loadB = [&](int buf, int koff) {
        const uint32_t sb = smb + buf * STAGE_BYTES;
        #pragma unroll
        for (int s2 = 0; s2 < 2; s2++) {
            for (int i = tid; i < 800; i += 128) {
                int row = i >> 2, seg = i & 3;
                uint32_t dst = sb + (OFF_BH + s2 * 8000 + row * ASTR + seg * 8) * 2;
                CP16(dst, Bsrc[s2] + (size_t)row * KTOT + koff + seg * 8);
            }
        }
    };

    loadA(0);
    loadB(0, 0);
    CP_COMMIT();
    stsA(0);

    const int brow = lane & 7;
    const int bk   = ((lane >> 3) & 1) * 8;
    const int bnhi = (lane >> 4) * 8;

    for (int ch = 0; ch < nch; ch++) {
        if (ch + 1 < nch) {
            loadA((ch + 1) * KCH);
            loadB((ch + 1) & 1, (ch + 1) * KCH);
        }
        CP_COMMIT();
        CP_WAIT1();
        __syncthreads();

        const uint32_t sb = smb + (ch & 1) * STAGE_BYTES;
        #pragma unroll
        for (int kk = 0; kk < 2; kk++) {
            uint32_t ah[4], am[4];
            uint32_t aaddr = sb + ((wid * 16 + (lane & 15)) * ASTR + kk * 16 + (lane >> 4) * 8) * 2;
            LDSM_X4(ah, aaddr);
            LDSM_X4(am, aaddr + OFF_AM * 2);

            #pragma unroll
            for (int i = 0; i < 12; i++) {
                uint32_t bh4[4], bm4[4];
                uint32_t ba = sb + (OFF_BH + (i * 16 + bnhi + brow) * ASTR + kk * 16 + bk) * 2;
                LDSM_X4(bh4, ba);
                LDSM_X4(bm4, ba + 8000 * 2);
                // interleaved across the pair: per-acc order stays hh, hm, mh
                MMA16816(acc[2 * i],     ah, bh4[0], bh4[1]);
                MMA16816(acc[2 * i + 1], ah, bh4[2], bh4[3]);
                MMA16816(acc[2 * i],     ah, bm4[0], bm4[1]);
                MMA16816(acc[2 * i + 1], ah, bm4[2], bm4[3]);
                MMA16816(acc[2 * i],     am, bh4[0], bh4[1]);
                MMA16816(acc[2 * i + 1], am, bh4[2], bh4[3]);
            }
            {
                uint32_t bh2[2], bm2[2];
                uint32_t ba = sb + (OFF_BH + (192 + brow) * ASTR + kk * 16 + bk) * 2;
                LDSM_X2(bh2, ba);
                LDSM_X2(bm2, ba + 8000 * 2);
                MMA16816(acc[24], ah, bh2[0], bh2[1]);
                MMA16816(acc[24], ah, bm2[0], bm2[1]);
                MMA16816(acc[24], am, bh2[0], bh2[1]);
            }
        }
        if (ch + 1 < nch) stsA((ch + 1) & 1);
        __syncthreads();
    }

    // Epilogue: global row = m_tile*64 + r0 -> t = row>>7, b = row&127
    const int r0 = wid * 16 + (lane >> 2);
    const int grow0 = m_tile * 64 + r0;
    #pragma unroll
    for (int half = 0; half < 2; half++) {
        const int grow = grow0 + half * 8;
        const int tt2 = grow >> 7, bb2 = grow & 127;
        float* dst = g_cur + (((size_t)tt2 * 9 + g) * BB + bb2) * HH;
        #pragma unroll
        for (int n = 0; n < 25; n++) {
            const int col = n * 8 + (lane & 3) * 2;
            float2 v2 = { acc[n][2 * half]     + bias[col],
                          acc[n][2 * half + 1] + bias[col + 1] };
            *(float2*)&dst[col] = v2;
        }
    }
}

// ---------------------------------------------------------------------------
// Kernel D: fused scan, 8x-unrolled timesteps (validated R11, unchanged).
// ---------------------------------------------------------------------------
#define SC_WO    0
#define SC_BO    2000
#define SC_CURO  2040
#define SC_ZS    2360
#define SC_PART  3960
#define SCAN_SMEM ((3960 + 8 * 1800) * 4)   // 73,440 bytes

__global__ __launch_bounds__(480)
void fused_scan_out(const float* __restrict__ Wout,
                    const float* __restrict__ bout,
                    float* __restrict__ out)
{
    extern __shared__ float dsm[];
    float* wo   = dsm + SC_WO;
    float* bo_s = dsm + SC_BO;
    float* curo = dsm + SC_CURO;     // [j][40]
    float* zs   = dsm + SC_ZS;       // [j][200]
    float* part = dsm + SC_PART;     // [j][1800]

    const int b   = blockIdx.x;
    const int tid = threadIdx.x;
    const bool scan_thr = tid < 450;
    const int h4 = scan_thr ? (tid % 50) : 0;
    const int br = scan_thr ? (tid / 50) : 0;

    for (int i = tid; i < 2000; i += 480) wo[i] = Wout[i];
    if (tid < 40) bo_s[tid] = bout[tid];

    float4 v  = {0.f, 0.f, 0.f, 0.f};
    float4 cc = {0.f, 0.f, 0.f, 0.f};
    float vo[4] = {0.f, 0.f, 0.f, 0.f};
    float io[4] = {0.f, 0.f, 0.f, 0.f};

    const float4* cur4 = (const float4*)g_cur;
    const size_t bh4 = (size_t)b * 50 + h4;

    float4 cin[2][8];
    if (scan_thr) {
        #pragma unroll
        for (int j = 0; j < 8; j++)
            cin[0][j] = cur4[(size_t)(j * 9 + br) * (BB * 50) + bh4];
    }
    __syncthreads();

    for (int r = 0; r < 8; r++) {
        const int buf = r & 1;
        if (scan_thr && r + 1 < 8) {
            #pragma unroll
            for (int j = 0; j < 8; j++)
                cin[buf ^ 1][j] = cur4[(size_t)((8 * (r + 1) + j) * 9 + br) * (BB * 50) + bh4];
        }

        if (scan_thr) {
            #pragma unroll
            for (int j = 0; j < 8; j++) {
                const float4 ci = cin[buf][j];
                float4 z;
                float vdx = v.x + 0.1f * (cc.x - v.x);
                float vdy = v.y + 0.1f * (cc.y - v.y);
                float vdz = v.z + 0.1f * (cc.z - v.z);
                float vdw = v.w + 0.1f * (cc.w - v.w);
                z.x = (vdx > 1.0f) ? 1.0f : 0.0f;  v.x = (vdx > 1.0f) ? 0.0f : vdx;
                z.y = (vdy > 1.0f) ? 1.0f : 0.0f;  v.y = (vdy > 1.0f) ? 0.0f : vdy;
                z.z = (vdz > 1.0f) ? 1.0f : 0.0f;  v.z = (vdz > 1.0f) ? 0.0f : vdz;
                z.w = (vdw > 1.0f) ? 1.0f : 0.0f;  v.w = (vdw > 1.0f) ? 0.0f : vdw;
                cc.x = 0.8f * cc.x + ci.x;
                cc.y = 0.8f * cc.y + ci.y;
                cc.z = 0.8f * cc.z + ci.z;
                cc.w = 0.8f * cc.w + ci.w;
                ((float4*)(part + j * 1800))[br * 50 + h4] = z;
            }
        }
        __syncthreads();

        if (tid < 400) {                      // reduce 9 branches, 8 t's
            const int j = tid / 50, hq = tid % 50;
            const float4* pj = (const float4*)(part + j * 1800);
            float4 s = pj[hq];
            #pragma unroll
            for (int r2 = 1; r2 < 9; r2++) {
                float4 q = pj[r2 * 50 + hq];
                s.x += q.x; s.y += q.y; s.z += q.z; s.w += q.w;
            }
            ((float4*)(zs + j * 200))[hq] = s;
        }
        __syncthreads();

        if (tid < 320) {                      // output GEMM: 8 t's x 40
            const int j = tid / 40, rem = tid % 40;
            const int k = rem / 10;
            const float2* zp = (const float2*)(zs + j * 200 + k * 50);
            const float2* wp = (const float2*)(wo + rem * 50);
            float s = bo_s[rem];
            #pragma unroll
            for (int q = 0; q < 25; q++) {
                float2 a = zp[q], ww = wp[q];
                s = fmaf(a.x, ww.x, s);
                s = fmaf(a.y, ww.y, s);
            }
            curo[j * 40 + rem] = s;
        }
        __syncthreads();

        if (tid < 10) {                       // LI readout, 8 sequential steps
            #pragma unroll
            for (int j = 0; j < 8; j++) {
                float s = 0.f;
                #pragma unroll
                for (int k = 0; k < 4; k++) {
                    vo[k] = vo[k] + 0.1f * (io[k] - vo[k]);
                    io[k] = 0.8f * io[k] + curo[j * 40 + k * 10 + tid];
                    s += vo[k];
                }
                out[((size_t)(8 * r + j) * BB + b) * 10 + tid] = s;
            }
        }
    }
}

// ---------------------------------------------------------------------------
extern "C" void kernel_launch(void* const* d_in, const int* in_sizes, int n_in,
                              void* d_out, int out_size)
{
    const float* x    = (const float*)d_in[0];
    const float* WL   = (const float*)d_in[1];
    const float* bL   = (const float*)d_in[2];
    const float* WM   = (const float*)d_in[3];
    const float* bM   = (const float*)d_in[4];
    const float* WR   = (const float*)d_in[5];
    const float* bR   = (const float*)d_in[6];
    const float* Wout = (const float*)d_in[7];
    const float* bout = (const float*)d_in[8];
    float* out = (float*)d_out;

    cudaFuncSetAttribute(gemm_mma, cudaFuncAttributeMaxDynamicSharedMemorySize, GEMM_SMEM);
    cudaFuncSetAttribute(fused_scan_out, cudaFuncAttributeMaxDynamicSharedMemorySize, SCAN_SMEM);

    convert_w<<<(3 * HH * 512 + 255) / 256, 256>>>(WL, WM, WR);
    gemm_mma<<<dim3(128, 9), 128, GEMM_SMEM>>>(x, bL, bM, bR);
    fused_scan_out<<<128, 480, SCAN_SMEM>>>(Wout, bout, out);
}

// round 16
// speedup vs baseline: 1.0165x; 1.0165x over previous
#include <cuda_runtime.h>
#include <cuda_fp16.h>
#include <cstdint>

#define TT 64
#define BB 128
#define HH 200
#define RROWS 8192      // T*B
#define KTOT 1024       // packed K per channel (320 L + 384 M + 320 R)

// ---------------------------------------------------------------------------
// Scratch (__device__ globals; no cudaMalloc allowed)
// ---------------------------------------------------------------------------
__device__ float g_cur[(size_t)TT * 9 * BB * HH];    // [t][g][b][h]
__device__ __half g_Bh[(size_t)3 * HH * KTOT];       // hi fp16 split of W (K-packed)
__device__ __half g_Bm[(size_t)3 * HH * KTOT];       // lo fp16 split

// ---------------------------------------------------------------------------
// PTX helpers (plain sm_103-compatible: mma.sync / ldmatrix / cp.async)
// ---------------------------------------------------------------------------
__device__ __forceinline__ uint32_t smem_u32(const void* p) {
    uint32_t a;
    asm("{ .reg .u64 t; cvta.to.shared.u64 t, %1; cvt.u32.u64 %0, t; }" : "=r"(a) : "l"(p));
    return a;
}

#define CP16(dst, src) \
    asm volatile("cp.async.cg.shared.global [%0], [%1], 16;" :: "r"(dst), "l"(src) : "memory")
#define CP_COMMIT() asm volatile("cp.async.commit_group;" ::: "memory")
#define CP_WAIT0()  asm volatile("cp.async.wait_group 0;" ::: "memory")

#define LDSM_X4(r, addr) \
    asm volatile("ldmatrix.sync.aligned.m8n8.x4.shared.b16 {%0,%1,%2,%3}, [%4];" \
        : "=r"((r)[0]), "=r"((r)[1]), "=r"((r)[2]), "=r"((r)[3]) : "r"(addr))
#define LDSM_X2(r, addr) \
    asm volatile("ldmatrix.sync.aligned.m8n8.x2.shared.b16 {%0,%1}, [%2];" \
        : "=r"((r)[0]), "=r"((r)[1]) : "r"(addr))

#define MMA16816(d, a, b0, b1) \
    asm volatile("mma.sync.aligned.m16n8k16.row.col.f32.f16.f16.f32 " \
        "{%0,%1,%2,%3},{%4,%5,%6,%7},{%8,%9},{%0,%1,%2,%3};" \
        : "+f"((d)[0]), "+f"((d)[1]), "+f"((d)[2]), "+f"((d)[3]) \
        : "r"((a)[0]), "r"((a)[1]), "r"((a)[2]), "r"((a)[3]), "r"(b0), "r"(b1))

// ---------------------------------------------------------------------------
// Kernel B: split weights into K-packed [c][h][1024] fp16 pairs.
//   float4 loads: quads (q..q+3) never cross part boundaries (0/320/704 all
//   multiples of 4, all part K's multiples of 4).
// ---------------------------------------------------------------------------
__global__ void convert_w(const float* __restrict__ WL, const float* __restrict__ WM,
                          const float* __restrict__ WR)
{
    int idx4 = blockIdx.x * 256 + threadIdx.x;
    if (idx4 >= 3 * HH * 256) return;
    int q4 = idx4 & 255;
    int ch = idx4 >> 8;                  // c*HH + h
    int q  = q4 * 4;
    float4 v;
    if (q < 320)      v = *(const float4*)&WL[(size_t)ch * 320 + q];
    else if (q < 704) v = *(const float4*)&WM[(size_t)ch * 384 + (q - 320)];
    else              v = *(const float4*)&WR[(size_t)ch * 320 + (q - 704)];
    __half h0 = __float2half_rn(v.x), h1 = __float2half_rn(v.y);
    __half h2 = __float2half_rn(v.z), h3 = __float2half_rn(v.w);
    __half m0 = __float2half_rn(v.x - __half2float(h0));
    __half m1 = __float2half_rn(v.y - __half2float(h1));
    __half m2 = __float2half_rn(v.z - __half2float(h2));
    __half m3 = __float2half_rn(v.w - __half2float(h3));
    uint2 ph, pm;
    ph.x = __half2uint_rn(0);  // placeholder, overwritten below
    *(__half2*)&ph.x = __halves2half2(h0, h1);
    *(__half2*)&ph.y = __halves2half2(h2, h3);
    *(__half2*)&pm.x = __halves2half2(m0, m1);
    *(__half2*)&pm.y = __halves2half2(m2, m3);
    *(uint2*)&g_Bh[(size_t)ch * KTOT + q] = ph;
    *(uint2*)&g_Bm[(size_t)ch * KTOT + q] = pm;
}

// ---------------------------------------------------------------------------
// Kernel C: HMMA GEMM, M=64 / 128 thr / 4 warps, 2 blocks per SM (R12 tiles).
//   ONE barrier per chunk: loadB + stsA moved after the leading sync, which
//   then fences all smem hazards; A prefetched distance-2 in registers so the
//   STS never waits on in-flight LDGs.  Per-element math and per-accumulator
//   addition order identical to R12/R14 (bitwise-identical output).
// ---------------------------------------------------------------------------
#define KCH   32
#define ASTR  40                          // halfs per smem row (A and B)
#define OFF_AM 2560                       // halfs: 64*40
#define OFF_BH 5120                       // halfs: 2*64*40
#define STAGE_HALFS 21120                 // 5120 + 2*8000
#define STAGE_BYTES (STAGE_HALFS * 2)     // 42240
#define GEMM_SMEM (2 * STAGE_BYTES)       // 84480  (x2 blocks = 168960)

__constant__ int c_gmap[9] = {3, 4, 5, 0, 1, 2, 6, 7, 8};   // M part first

__global__ __launch_bounds__(128, 2)
void gemm_mma(const float* __restrict__ x,
              const float* __restrict__ bL, const float* __restrict__ bM,
              const float* __restrict__ bR)
{
    extern __shared__ __half sm[];
    __shared__ int colmap[192];           // x column for even local-q pairs
    const uint32_t smb = smem_u32(sm);
    const int tid = threadIdx.x, wid = tid >> 5, lane = tid & 31;
    const int m_tile = blockIdx.x;        // 0..127, rows m_tile*64..+64
    const int g = c_gmap[blockIdx.y], p = g / 3, c = g - p * 3;

    int Kp, q0, w, off;
    const float* bias;
    if (p == 0)      { Kp = 320; q0 = 0;   w = 10; off = 0;  bias = bL; }
    else if (p == 1) { Kp = 384; q0 = 320; w = 12; off = 10; bias = bM; }
    else             { Kp = 320; q0 = 704; w = 10; off = 22; bias = bR; }
    bias += c * HH;
    const int nch = Kp / KCH;

    for (int q2 = tid; q2 < Kp / 2; q2 += 128) {
        int ql = q2 * 2;
        int grp = ql / w, l = ql - grp * w;
        colmap[q2] = grp * 32 + off + l;
    }
    __syncthreads();

    const float* xc = x + (size_t)m_tile * 64 * 3072 + (size_t)c * 1024;
    const size_t bbase = (size_t)c * HH * KTOT + q0;
    const __half* Bsrc[2] = { g_Bh + bbase, g_Bm + bbase };

    float acc[25][4];
    #pragma unroll
    for (int n = 0; n < 25; n++)
        #pragma unroll
        for (int j = 0; j < 4; j++) acc[n][j] = 0.f;

    // A: 64 rows x 16 float2 = 1024 float2 / 128 thr = 8 per thread
    float2 areg[8];
    auto loadA = [&](int koff) {
        #pragma unroll
        for (int s = 0; s < 8; s++) {
            int i = tid + s * 128;
            int row = i >> 4, j = i & 15;
            areg[s] = *(const float2*)(xc + (size_t)row * 3072 + colmap[(koff >> 1) + j]);
        }
    };
    auto stsA = [&](int buf) {
        __half* base = sm + buf * STAGE_HALFS;
        #pragma unroll
        for (int s = 0; s < 8; s++) {
            int i = tid + s * 128;
            int row = i >> 4, j = i & 15;
            float vx = areg[s].x, vy = areg[s].y;
            __half hx = __float2half_rn(vx), hy = __float2half_rn(vy);
            __half mx = __float2half_rn(vx - __half2float(hx));
            __half my = __float2half_rn(vy - __half2float(hy));
            int pos = row * ASTR + j * 2;
            *(__half2*)(base + pos)          = __halves2half2(hx, hy);
            *(__half2*)(base + OFF_AM + pos) = __halves2half2(mx, my);
        }
    };
    auto loadB = [&](int buf, int koff) {
        const uint32_t sb = smb + buf * STAGE_BYTES;
        #pragma unroll
        for (int s2 = 0; s2 < 2; s2++) {
            for (int i = tid; i < 800; i += 128) {
                int row = i >> 2, seg = i & 3;
                uint32_t dst = sb + (OFF_BH + s2 * 8000 + row * ASTR + seg * 8) * 2;
                CP16(dst, Bsrc[s2] + (size_t)row * KTOT + koff + seg * 8);
            }
        }
    };

    // Prologue: A(0) staged; A(1) prefetched to regs; B(0) in flight.
    loadA(0);
    loadB(0, 0);
    CP_COMMIT();
    stsA(0);                               // stalls on A(0) LDGs (kernel start)
    loadA(KCH);                            // A(1) -> regs (nch >= 10 always)

    const int brow = lane & 7;
    const int bk   = ((lane >> 3) & 1) * 8;
    const int bnhi = (lane >> 4) * 8;

    for (int ch = 0; ch < nch; ch++) {
        CP_WAIT0();                        // B(ch) landed (only group in flight)
        __syncthreads();                   // fences: A-sts(ch) visible; iter ch-1
                                           // readers of A-buf/B-buf (ch+1)&1 done
        if (ch + 1 < nch) {
            loadB((ch + 1) & 1, (ch + 1) * KCH);   // overlaps compute below
            CP_COMMIT();
            stsA((ch + 1) & 1);            // areg = A(ch+1), resident since iter ch-1
            if (ch + 2 < nch) loadA((ch + 2) * KCH);   // A(ch+2) -> regs
        }

        const uint32_t sb = smb + (ch & 1) * STAGE_BYTES;
        #pragma unroll
        for (int kk = 0; kk < 2; kk++) {
            uint32_t ah[4], am[4];
            uint32_t aaddr = sb + ((wid * 16 + (lane & 15)) * ASTR + kk * 16 + (lane >> 4) * 8) * 2;
            LDSM_X4(ah, aaddr);
            LDSM_X4(am, aaddr + OFF_AM * 2);

            #pragma unroll
            for (int i = 0; i < 12; i++) {
                uint32_t bh4[4], bm4[4];
                uint32_t ba = sb + (OFF_BH + (i * 16 + bnhi + brow) * ASTR + kk * 16 + bk) * 2;
                LDSM_X4(bh4, ba);
                LDSM_X4(bm4, ba + 8000 * 2);
                MMA16816(acc[2 * i],     ah, bh4[0], bh4[1]);
                MMA16816(acc[2 * i],     ah, bm4[0], bm4[1]);
                MMA16816(acc[2 * i],     am, bh4[0], bh4[1]);
                MMA16816(acc[2 * i + 1], ah, bh4[2], bh4[3]);
                MMA16816(acc[2 * i + 1], ah, bm4[2], bm4[3]);
                MMA16816(acc[2 * i + 1], am, bh4[2], bh4[3]);
            }
            {
                uint32_t bh2[2], bm2[2];
                uint32_t ba = sb + (OFF_BH + (192 + brow) * ASTR + kk * 16 + bk) * 2;
                LDSM_X2(bh2, ba);
                LDSM_X2(bm2, ba + 8000 * 2);
                MMA16816(acc[24], ah, bh2[0], bh2[1]);
                MMA16816(acc[24], ah, bm2[0], bm2[1]);
                MMA16816(acc[24], am, bh2[0], bh2[1]);
            }
        }
        // no trailing sync: next iteration's leading sync covers all hazards
    }

    // Epilogue: global row = m_tile*64 + r0 -> t = row>>7, b = row&127
    const int r0 = wid * 16 + (lane >> 2);
    const int grow0 = m_tile * 64 + r0;
    #pragma unroll
    for (int half = 0; half < 2; half++) {
        const int grow = grow0 + half * 8;
        const int tt2 = grow >> 7, bb2 = grow & 127;
        float* dst = g_cur + (((size_t)tt2 * 9 + g) * BB + bb2) * HH;
        #pragma unroll
        for (int n = 0; n < 25; n++) {
            const int col = n * 8 + (lane & 3) * 2;
            float2 v2 = { acc[n][2 * half]     + bias[col],
                          acc[n][2 * half + 1] + bias[col + 1] };
            *(float2*)&dst[col] = v2;
        }
    }
}

// ---------------------------------------------------------------------------
// Kernel D: fused scan, 8x-unrolled timesteps (validated R11, unchanged).
// ---------------------------------------------------------------------------
#define SC_WO    0
#define SC_BO    2000
#define SC_CURO  2040
#define SC_ZS    2360
#define SC_PART  3960
#define SCAN_SMEM ((3960 + 8 * 1800) * 4)   // 73,440 bytes

__global__ __launch_bounds__(480)
void fused_scan_out(const float* __restrict__ Wout,
                    const float* __restrict__ bout,
                    float* __restrict__ out)
{
    extern __shared__ float dsm[];
    float* wo   = dsm + SC_WO;
    float* bo_s = dsm + SC_BO;
    float* curo = dsm + SC_CURO;     // [j][40]
    float* zs   = dsm + SC_ZS;       // [j][200]
    float* part = dsm + SC_PART;     // [j][1800]

    const int b   = blockIdx.x;
    const int tid = threadIdx.x;
    const bool scan_thr = tid < 450;
    const int h4 = scan_thr ? (tid % 50) : 0;
    const int br = scan_thr ? (tid / 50) : 0;

    for (int i = tid; i < 2000; i += 480) wo[i] = Wout[i];
    if (tid < 40) bo_s[tid] = bout[tid];

    float4 v  = {0.f, 0.f, 0.f, 0.f};
    float4 cc = {0.f, 0.f, 0.f, 0.f};
    float vo[4] = {0.f, 0.f, 0.f, 0.f};
    float io[4] = {0.f, 0.f, 0.f, 0.f};

    const float4* cur4 = (const float4*)g_cur;
    const size_t bh4 = (size_t)b * 50 + h4;

    float4 cin[2][8];
    if (scan_thr) {
        #pragma unroll
        for (int j = 0; j < 8; j++)
            cin[0][j] = cur4[(size_t)(j * 9 + br) * (BB * 50) + bh4];
    }
    __syncthreads();

    for (int r = 0; r < 8; r++) {
        const int buf = r & 1;
        if (scan_thr && r + 1 < 8) {
            #pragma unroll
            for (int j = 0; j < 8; j++)
                cin[buf ^ 1][j] = cur4[(size_t)((8 * (r + 1) + j) * 9 + br) * (BB * 50) + bh4];
        }

        if (scan_thr) {
            #pragma unroll
            for (int j = 0; j < 8; j++) {
                const float4 ci = cin[buf][j];
                float4 z;
                float vdx = v.x + 0.1f * (cc.x - v.x);
                float vdy = v.y + 0.1f * (cc.y - v.y);
                float vdz = v.z + 0.1f * (cc.z - v.z);
                float vdw = v.w + 0.1f * (cc.w - v.w);
                z.x = (vdx > 1.0f) ? 1.0f : 0.0f;  v.x = (vdx > 1.0f) ? 0.0f : vdx;
                z.y = (vdy > 1.0f) ? 1.0f : 0.0f;  v.y = (vdy > 1.0f) ? 0.0f : vdy;
                z.z = (vdz > 1.0f) ? 1.0f : 0.0f;  v.z = (vdz > 1.0f) ? 0.0f : vdz;
                z.w = (vdw > 1.0f) ? 1.0f : 0.0f;  v.w = (vdw > 1.0f) ? 0.0f : vdw;
                cc.x = 0.8f * cc.x + ci.x;
                cc.y = 0.8f * cc.y + ci.y;
                cc.z = 0.8f * cc.z + ci.z;
                cc.w = 0.8f * cc.w + ci.w;
                ((float4*)(part + j * 1800))[br * 50 + h4] = z;
            }
        }
        __syncthreads();

        if (tid < 400) {                      // reduce 9 branches, 8 t's
            const int j = tid / 50, hq = tid % 50;
            const float4* pj = (const float4*)(part + j * 1800);
            float4 s = pj[hq];
            #pragma unroll
            for (int r2 = 1; r2 < 9; r2++) {
                float4 q = pj[r2 * 50 + hq];
                s.x += q.x; s.y += q.y; s.z += q.z; s.w += q.w;
            }
            ((float4*)(zs + j * 200))[hq] = s;
        }
        __syncthreads();

        if (tid < 320) {                      // output GEMM: 8 t's x 40
            const int j = tid / 40, rem = tid % 40;
            const int k = rem / 10;
            const float2* zp = (const float2*)(zs + j * 200 + k * 50);
            const float2* wp = (const float2*)(wo + rem * 50);
            float s = bo_s[rem];
            #pragma unroll
            for (int q = 0; q < 25; q++) {
                float2 a = zp[q], ww = wp[q];
                s = fmaf(a.x, ww.x, s);
                s = fmaf(a.y, ww.y, s);
            }
            curo[j * 40 + rem] = s;
        }
        __syncthreads();

        if (tid < 10) {                       // LI readout, 8 sequential steps
            #pragma unroll
            for (int j = 0; j < 8; j++) {
                float s = 0.f;
                #pragma unroll
                for (int k = 0; k < 4; k++) {
                    vo[k] = vo[k] + 0.1f * (io[k] - vo[k]);
                    io[k] = 0.8f * io[k] + curo[j * 40 + k * 10 + tid];
                    s += vo[k];
                }
                out[((size_t)(8 * r + j) * BB + b) * 10 + tid] = s;
            }
        }
    }
}

// ---------------------------------------------------------------------------
extern "C" void kernel_launch(void* const* d_in, const int* in_sizes, int n_in,
                              void* d_out, int out_size)
{
    const float* x    = (const float*)d_in[0];
    const float* WL   = (const float*)d_in[1];
    const float* bL   = (const float*)d_in[2];
    const float* WM   = (const float*)d_in[3];
    const float* bM   = (const float*)d_in[4];
    const float* WR   = (const float*)d_in[5];
    const float* bR   = (const float*)d_in[6];
    const float* Wout = (const float*)d_in[7];
    const float* bout = (const float*)d_in[8];
    float* out = (float*)d_out;

    cudaFuncSetAttribute(gemm_mma, cudaFuncAttributeMaxDynamicSharedMemorySize, GEMM_SMEM);
    cudaFuncSetAttribute(fused_scan_out, cudaFuncAttributeMaxDynamicSharedMemorySize, SCAN_SMEM);

    convert_w<<<(3 * HH * 256 + 255) / 256, 256>>>(WL, WM, WR);
    gemm_mma<<<dim3(128, 9), 128, GEMM_SMEM>>>(x, bL, bM, bR);
    fused_scan_out<<<128, 480, SCAN_SMEM>>>(Wout, bout, out);
}

// round 17
// speedup vs baseline: 1.0365x; 1.0196x over previous
#include <cuda_runtime.h>
#include <cuda_fp16.h>
#include <cstdint>

#define TT 64
#define BB 128
#define HH 200
#define RROWS 8192      // T*B
#define KTOT 1024       // packed K per channel (320 L + 384 M + 320 R)

// ---------------------------------------------------------------------------
// Scratch (__device__ globals; no cudaMalloc allowed)
// ---------------------------------------------------------------------------
__device__ float g_cur[(size_t)TT * 9 * BB * HH];    // [t][g][b][h]
__device__ __half g_Bh[(size_t)3 * HH * KTOT];       // hi fp16 split of W (K-packed)
__device__ __half g_Bm[(size_t)3 * HH * KTOT];       // lo fp16 split

// ---------------------------------------------------------------------------
// PTX helpers (plain sm_103-compatible: mma.sync / ldmatrix / cp.async)
// ---------------------------------------------------------------------------
__device__ __forceinline__ uint32_t smem_u32(const void* p) {
    uint32_t a;
    asm("{ .reg .u64 t; cvta.to.shared.u64 t, %1; cvt.u32.u64 %0, t; }" : "=r"(a) : "l"(p));
    return a;
}

#define CP16(dst, src) \
    asm volatile("cp.async.cg.shared.global [%0], [%1], 16;" :: "r"(dst), "l"(src) : "memory")
#define CP_COMMIT() asm volatile("cp.async.commit_group;" ::: "memory")
#define CP_WAIT0()  asm volatile("cp.async.wait_group 0;" ::: "memory")

#define LDSM_X4(r, addr) \
    asm volatile("ldmatrix.sync.aligned.m8n8.x4.shared.b16 {%0,%1,%2,%3}, [%4];" \
        : "=r"((r)[0]), "=r"((r)[1]), "=r"((r)[2]), "=r"((r)[3]) : "r"(addr))
#define LDSM_X2(r, addr) \
    asm volatile("ldmatrix.sync.aligned.m8n8.x2.shared.b16 {%0,%1}, [%2];" \
        : "=r"((r)[0]), "=r"((r)[1]) : "r"(addr))

#define MMA16816(d, a, b0, b1) \
    asm volatile("mma.sync.aligned.m16n8k16.row.col.f32.f16.f16.f32 " \
        "{%0,%1,%2,%3},{%4,%5,%6,%7},{%8,%9},{%0,%1,%2,%3};" \
        : "+f"((d)[0]), "+f"((d)[1]), "+f"((d)[2]), "+f"((d)[3]) \
        : "r"((a)[0]), "r"((a)[1]), "r"((a)[2]), "r"((a)[3]), "r"(b0), "r"(b1))

// ---------------------------------------------------------------------------
// Kernel B: split weights into K-packed fp16 pairs (float4) + zero d_out.
// ---------------------------------------------------------------------------
__global__ void convert_w(const float* __restrict__ WL, const float* __restrict__ WM,
                          const float* __restrict__ WR, float* __restrict__ out)
{
    int idx4 = blockIdx.x * 256 + threadIdx.x;
    if (idx4 < TT * BB * 10) out[idx4] = 0.f;          // 81920 out elements
    if (idx4 >= 3 * HH * 256) return;
    int q4 = idx4 & 255;
    int ch = idx4 >> 8;                  // c*HH + h
    int q  = q4 * 4;
    float4 v;
    if (q < 320)      v = *(const float4*)&WL[(size_t)ch * 320 + q];
    else if (q < 704) v = *(const float4*)&WM[(size_t)ch * 384 + (q - 320)];
    else              v = *(const float4*)&WR[(size_t)ch * 320 + (q - 704)];
    __half h0 = __float2half_rn(v.x), h1 = __float2half_rn(v.y);
    __half h2 = __float2half_rn(v.z), h3 = __float2half_rn(v.w);
    __half m0 = __float2half_rn(v.x - __half2float(h0));
    __half m1 = __float2half_rn(v.y - __half2float(h1));
    __half m2 = __float2half_rn(v.z - __half2float(h2));
    __half m3 = __float2half_rn(v.w - __half2float(h3));
    uint2 ph, pm;
    *(__half2*)&ph.x = __halves2half2(h0, h1);
    *(__half2*)&ph.y = __halves2half2(h2, h3);
    *(__half2*)&pm.x = __halves2half2(m0, m1);
    *(__half2*)&pm.y = __halves2half2(m2, m3);
    *(uint2*)&g_Bh[(size_t)ch * KTOT + q] = ph;
    *(uint2*)&g_Bm[(size_t)ch * KTOT + q] = pm;
}

// ---------------------------------------------------------------------------
// Kernel C: HMMA GEMM — byte-identical to R16 (measured best).
// ---------------------------------------------------------------------------
#define KCH   32
#define ASTR  40                          // halfs per smem row (A and B)
#define OFF_AM 2560                       // halfs: 64*40
#define OFF_BH 5120                       // halfs: 2*64*40
#define STAGE_HALFS 21120                 // 5120 + 2*8000
#define STAGE_BYTES (STAGE_HALFS * 2)     // 42240
#define GEMM_SMEM (2 * STAGE_BYTES)       // 84480  (x2 blocks = 168960)

__constant__ int c_gmap[9] = {3, 4, 5, 0, 1, 2, 6, 7, 8};   // M part first

__global__ __launch_bounds__(128, 2)
void gemm_mma(const float* __restrict__ x,
              const float* __restrict__ bL, const float* __restrict__ bM,
              const float* __restrict__ bR)
{
    extern __shared__ __half sm[];
    __shared__ int colmap[192];           // x column for even local-q pairs
    const uint32_t smb = smem_u32(sm);
    const int tid = threadIdx.x, wid = tid >> 5, lane = tid & 31;
    const int m_tile = blockIdx.x;        // 0..127, rows m_tile*64..+64
    const int g = c_gmap[blockIdx.y], p = g / 3, c = g - p * 3;

    int Kp, q0, w, off;
    const float* bias;
    if (p == 0)      { Kp = 320; q0 = 0;   w = 10; off = 0;  bias = bL; }
    else if (p == 1) { Kp = 384; q0 = 320; w = 12; off = 10; bias = bM; }
    else             { Kp = 320; q0 = 704; w = 10; off = 22; bias = bR; }
    bias += c * HH;
    const int nch = Kp / KCH;

    for (int q2 = tid; q2 < Kp / 2; q2 += 128) {
        int ql = q2 * 2;
        int grp = ql / w, l = ql - grp * w;
        colmap[q2] = grp * 32 + off + l;
    }
    __syncthreads();

    const float* xc = x + (size_t)m_tile * 64 * 3072 + (size_t)c * 1024;
    const size_t bbase = (size_t)c * HH * KTOT + q0;
    const __half* Bsrc[2] = { g_Bh + bbase, g_Bm + bbase };

    float acc[25][4];
    #pragma unroll
    for (int n = 0; n < 25; n++)
        #pragma unroll
        for (int j = 0; j < 4; j++) acc[n][j] = 0.f;

    float2 areg[8];
    auto loadA = [&](int koff) {
        #pragma unroll
        for (int s = 0; s < 8; s++) {
            int i = tid + s * 128;
            int row = i >> 4, j = i & 15;
            areg[s] = *(const float2*)(xc + (size_t)row * 3072 + colmap[(koff >> 1) + j]);
        }
    };
    auto stsA = [&](int buf) {
        __half* base = sm + buf * STAGE_HALFS;
        #pragma unroll
        for (int s = 0; s < 8; s++) {
            int i = tid + s * 128;
            int row = i >> 4, j = i & 15;
            float vx = areg[s].x, vy = areg[s].y;
            __half hx = __float2half_rn(vx), hy = __float2half_rn(vy);
            __half mx = __float2half_rn(vx - __half2float(hx));
            __half my = __float2half_rn(vy - __half2float(hy));
            int pos = row * ASTR + j * 2;
            *(__half2*)(base + pos)          = __halves2half2(hx, hy);
            *(__half2*)(base + OFF_AM + pos) = __halves2half2(mx, my);
        }
    };
    auto loadB = [&](int buf, int koff) {
        const uint32_t sb = smb + buf * STAGE_BYTES;
        #pragma unroll
        for (int s2 = 0; s2 < 2; s2++) {
            for (int i = tid; i < 800; i += 128) {
                int row = i >> 2, seg = i & 3;
                uint32_t dst = sb + (OFF_BH + s2 * 8000 + row * ASTR + seg * 8) * 2;
                CP16(dst, Bsrc[s2] + (size_t)row * KTOT + koff + seg * 8);
            }
        }
    };

    // Prologue: A(0) staged; A(1) prefetched to regs; B(0) in flight.
    loadA(0);
    loadB(0, 0);
    CP_COMMIT();
    stsA(0);
    loadA(KCH);

    const int brow = lane & 7;
    const int bk   = ((lane >> 3) & 1) * 8;
    const int bnhi = (lane >> 4) * 8;

    for (int ch = 0; ch < nch; ch++) {
        CP_WAIT0();                        // B(ch) landed
        __syncthreads();                   // single barrier fences all hazards
        if (ch + 1 < nch) {
            loadB((ch + 1) & 1, (ch + 1) * KCH);
            CP_COMMIT();
            stsA((ch + 1) & 1);
            if (ch + 2 < nch) loadA((ch + 2) * KCH);
        }

        const uint32_t sb = smb + (ch & 1) * STAGE_BYTES;
        #pragma unroll
        for (int kk = 0; kk < 2; kk++) {
            uint32_t ah[4], am[4];
            uint32_t aaddr = sb + ((wid * 16 + (lane & 15)) * ASTR + kk * 16 + (lane >> 4) * 8) * 2;
            LDSM_X4(ah, aaddr);
            LDSM_X4(am, aaddr + OFF_AM * 2);

            #pragma unroll
            for (int i = 0; i < 12; i++) {
                uint32_t bh4[4], bm4[4];
                uint32_t ba = sb + (OFF_BH + (i * 16 + bnhi + brow) * ASTR + kk * 16 + bk) * 2;
                LDSM_X4(bh4, ba);
                LDSM_X4(bm4, ba + 8000 * 2);
                MMA16816(acc[2 * i],     ah, bh4[0], bh4[1]);
                MMA16816(acc[2 * i],     ah, bm4[0], bm4[1]);
                MMA16816(acc[2 * i],     am, bh4[0], bh4[1]);
                MMA16816(acc[2 * i + 1], ah, bh4[2], bh4[3]);
                MMA16816(acc[2 * i + 1], ah, bm4[2], bm4[3]);
                MMA16816(acc[2 * i + 1], am, bh4[2], bh4[3]);
            }
            {
                uint32_t bh2[2], bm2[2];
                uint32_t ba = sb + (OFF_BH + (192 + brow) * ASTR + kk * 16 + bk) * 2;
                LDSM_X2(bh2, ba);
                LDSM_X2(bm2, ba + 8000 * 2);
                MMA16816(acc[24], ah, bh2[0], bh2[1]);
                MMA16816(acc[24], ah, bm2[0], bm2[1]);
                MMA16816(acc[24], am, bh2[0], bh2[1]);
            }
        }
    }

    const int r0 = wid * 16 + (lane >> 2);
    const int grow0 = m_tile * 64 + r0;
    #pragma unroll
    for (int half = 0; half < 2; half++) {
        const int grow = grow0 + half * 8;
        const int tt2 = grow >> 7, bb2 = grow & 127;
        float* dst = g_cur + (((size_t)tt2 * 9 + g) * BB + bb2) * HH;
        #pragma unroll
        for (int n = 0; n < 25; n++) {
            const int col = n * 8 + (lane & 3) * 2;
            float2 v2 = { acc[n][2 * half]     + bias[col],
                          acc[n][2 * half + 1] + bias[col + 1] };
            *(float2*)&dst[col] = v2;
        }
    }
}

// ---------------------------------------------------------------------------
// Kernel D: fused scan, 8x-unrolled, SPLIT over h: grid (128 b, 2 kh).
//   Block (b, kh) owns h = kh*100 .. +100 (k-groups 2kh, 2kh+1); its partial
//   sum of vo is atomicAdd-ed into out (zeroed by convert_w).  Two commuting
//   adds of the same values -> deterministic & exact.
// ---------------------------------------------------------------------------
__global__ __launch_bounds__(256)
void fused_scan_out(const float* __restrict__ Wout,
                    const float* __restrict__ bout,
                    float* __restrict__ out)
{
    __shared__ float wo[1000];        // Wout slice for this kh: [2 k][10 o][50]
    __shared__ float bo_s[20];
    __shared__ float4 part[8][225];   // z partials [j][br*25+q]
    __shared__ float zs[8][100];      // z_sum [j][hh]
    __shared__ float curo[8][20];     // cur_o [j][kl*10+o]

    const int b   = blockIdx.x;
    const int kh  = blockIdx.y;       // 0: h 0..99, 1: h 100..199
    const int tid = threadIdx.x;
    const bool scan_thr = tid < 225;
    const int q  = scan_thr ? (tid % 25) : 0;    // h-quad within half
    const int br = scan_thr ? (tid / 25) : 0;

    for (int i = tid; i < 1000; i += 256) wo[i] = Wout[kh * 1000 + i];
    if (tid < 20) bo_s[tid] = bout[kh * 20 + tid];

    float4 v  = {0.f, 0.f, 0.f, 0.f};
    float4 cc = {0.f, 0.f, 0.f, 0.f};
    float vo[2] = {0.f, 0.f};
    float io[2] = {0.f, 0.f};

    const float4* cur4 = (const float4*)g_cur;
    // float4 index: ((t*9+br)*128 + b)*50 + kh*25 + q
    const size_t bh4 = (size_t)b * 50 + kh * 25 + q;

    float4 cin[2][8];
    if (scan_thr) {
        #pragma unroll
        for (int j = 0; j < 8; j++)
            cin[0][j] = cur4[(size_t)(j * 9 + br) * (BB * 50) + bh4];
    }
    __syncthreads();

    for (int r = 0; r < 8; r++) {
        const int buf = r & 1;
        if (scan_thr && r + 1 < 8) {
            #pragma unroll
            for (int j = 0; j < 8; j++)
                cin[buf ^ 1][j] = cur4[(size_t)((8 * (r + 1) + j) * 9 + br) * (BB * 50) + bh4];
        }

        if (scan_thr) {
            #pragma unroll
            for (int j = 0; j < 8; j++) {
                const float4 ci = cin[buf][j];
                float4 z;
                float vdx = v.x + 0.1f * (cc.x - v.x);
                float vdy = v.y + 0.1f * (cc.y - v.y);
                float vdz = v.z + 0.1f * (cc.z - v.z);
                float vdw = v.w + 0.1f * (cc.w - v.w);
                z.x = (vdx > 1.0f) ? 1.0f : 0.0f;  v.x = (vdx > 1.0f) ? 0.0f : vdx;
                z.y = (vdy > 1.0f) ? 1.0f : 0.0f;  v.y = (vdy > 1.0f) ? 0.0f : vdy;
                z.z = (vdz > 1.0f) ? 1.0f : 0.0f;  v.z = (vdz > 1.0f) ? 0.0f : vdz;
                z.w = (vdw > 1.0f) ? 1.0f : 0.0f;  v.w = (vdw > 1.0f) ? 0.0f : vdw;
                cc.x = 0.8f * cc.x + ci.x;
                cc.y = 0.8f * cc.y + ci.y;
                cc.z = 0.8f * cc.z + ci.z;
                cc.w = 0.8f * cc.w + ci.w;
                part[j][br * 25 + q] = z;
            }
        }
        __syncthreads();

        if (tid < 200) {                      // reduce 9 branches: 8 j x 25 q
            const int j = tid / 25, hq = tid % 25;
            float4 s = part[j][hq];
            #pragma unroll
            for (int r2 = 1; r2 < 9; r2++) {
                float4 qv = part[j][r2 * 25 + hq];
                s.x += qv.x; s.y += qv.y; s.z += qv.z; s.w += qv.w;
            }
            ((float4*)zs[j])[hq] = s;
        }
        __syncthreads();

        if (tid < 160) {                      // output GEMM: 8 j x 20 (2k x 10o)
            const int j = tid / 20, rem = tid % 20;
            const int kl = rem / 10;
            const float2* zp = (const float2*)&zs[j][kl * 50];
            const float2* wp = (const float2*)&wo[rem * 50];
            float s = bo_s[rem];
            #pragma unroll
            for (int qq = 0; qq < 25; qq++) {
                float2 a = zp[qq], ww = wp[qq];
                s = fmaf(a.x, ww.x, s);
                s = fmaf(a.y, ww.y, s);
            }
            curo[j][rem] = s;
        }
        __syncthreads();

        if (tid < 10) {                       // LI readout, 2 local k states
            #pragma unroll
            for (int j = 0; j < 8; j++) {
                float s = 0.f;
                #pragma unroll
                for (int kl = 0; kl < 2; kl++) {
                    vo[kl] = vo[kl] + 0.1f * (io[kl] - vo[kl]);
                    io[kl] = 0.8f * io[kl] + curo[j][kl * 10 + tid];
                    s += vo[kl];
                }
                atomicAdd(&out[((size_t)(8 * r + j) * BB + b) * 10 + tid], s);
            }
        }
    }
}

// ---------------------------------------------------------------------------
extern "C" void kernel_launch(void* const* d_in, const int* in_sizes, int n_in,
                              void* d_out, int out_size)
{
    const float* x    = (const float*)d_in[0];
    const float* WL   = (const float*)d_in[1];
    const float* bL   = (const float*)d_in[2];
    const float* WM   = (const float*)d_in[3];
    const float* bM   = (const float*)d_in[4];
    const float* WR   = (const float*)d_in[5];
    const float* bR   = (const float*)d_in[6];
    const float* Wout = (const float*)d_in[7];
    const float* bout = (const float*)d_in[8];
    float* out = (float*)d_out;

    cudaFuncSetAttribute(gemm_mma, cudaFuncAttributeMaxDynamicSharedMemorySize, GEMM_SMEM);

    convert_w<<<(3 * HH * 256 + 255) / 256, 256>>>(WL, WM, WR, out);
    gemm_mma<<<dim3(128, 9), 128, GEMM_SMEM>>>(x, bL, bM, bR);
    fused_scan_out<<<dim3(128, 2), 256>>>(Wout, bout, out);
}